// round 5
// baseline (speedup 1.0000x reference)
#include <cuda_runtime.h>
#include <math.h>
#include <stdint.h>

// Problem constants (fixed shapes per reference)
#define DEPTH    8
#define NN       255      // internal nodes = 2^8 - 1
#define NL       256      // leaves
#define NCLS     200      // classes
#define BT       16       // batch tile per block

// smem layout (floats), padded strides for bank-conflict-free access
#define ER_OFF    0            // exp(sim)            [255][17]
#define ELP_OFF   4335         // -expm1(-(|s|+eps))  [255][17]
#define EW_OFF    8672         // path probs          [256][20]  (16B aligned)
#define ELS_OFF   13792        // EL k-chunk          [64][204]  (16B aligned)
#define SMEM_FLOATS (ELS_OFF + 64 * 204)   // 26848 floats = 107392 bytes

// softmax(leaf_logits) staged between kernels
__device__ __align__(16) float g_EL[NL * NCLS];

// ---------------- packed f32x2 helpers (Blackwell) ----------------
__device__ __forceinline__ unsigned long long pk2(float lo, float hi) {
    unsigned long long r;
    asm("mov.b64 %0, {%1, %2};" : "=l"(r) : "f"(lo), "f"(hi));
    return r;
}
__device__ __forceinline__ unsigned long long fma2(unsigned long long a,
                                                   unsigned long long b,
                                                   unsigned long long c) {
    unsigned long long d;
    asm("fma.rn.f32x2 %0, %1, %2, %3;" : "=l"(d) : "l"(a), "l"(b), "l"(c));
    return d;
}
__device__ __forceinline__ void upk2(unsigned long long v, float& lo, float& hi) {
    asm("mov.b64 {%0, %1}, %2;" : "=f"(lo), "=f"(hi) : "l"(v));
}

// ---------------- kernel 1: row softmax of leaf_logits ----------------
// one warp per leaf; 8 warps/block; 32 blocks
__global__ void leaf_softmax_kernel(const float* __restrict__ logits) {
    const int wid  = threadIdx.x >> 5;
    const int lane = threadIdx.x & 31;
    const int leaf = blockIdx.x * 8 + wid;
    const float* row = logits + leaf * NCLS;

    float v[7];
    float m = -INFINITY;
#pragma unroll
    for (int i = 0; i < 7; i++) {
        int c = lane + 32 * i;
        v[i] = (c < NCLS) ? row[c] : -INFINITY;
        m = fmaxf(m, v[i]);
    }
#pragma unroll
    for (int o = 16; o; o >>= 1) m = fmaxf(m, __shfl_xor_sync(0xffffffffu, m, o));

    float s = 0.f;
#pragma unroll
    for (int i = 0; i < 7; i++) {
        v[i] = expf(v[i] - m);   // exp(-inf - m) == 0 for padded entries
        s += v[i];
    }
#pragma unroll
    for (int o = 16; o; o >>= 1) s += __shfl_xor_sync(0xffffffffu, s, o);

    const float r = 1.0f / s;
#pragma unroll
    for (int i = 0; i < 7; i++) {
        int c = lane + 32 * i;
        if (c < NCLS) g_EL[leaf * NCLS + c] = v[i] * r;
    }
}

// ---------------- kernel 2: fused tree-walk + GEMM + log ----------------
// grid = B/16 blocks, 256 threads. Per block: out tile [16 batch][200 classes].
__global__ __launch_bounds__(256, 1)
void tree_gemm_kernel(const float* __restrict__ sims, float* __restrict__ out,
                      const int B) {
    extern __shared__ float sm[];
    float* s_er  = sm + ER_OFF;    // [node][b], stride 17
    float* s_elp = sm + ELP_OFF;   // [node][b], stride 17
    float* s_ew  = sm + EW_OFF;    // [leaf][b], stride 20
    float* s_els = sm + ELS_OFF;   // [kk][c],  stride 204

    const int b0 = blockIdx.x * BT;

    // ---- Phase A: load sims tile, convert to routing probabilities ----
    for (int i = threadIdx.x; i < NN * BT; i += 256) {
        const int n = i >> 4;
        const int b = i & 15;
        float s = 0.0f;
        if (b0 + b < B) s = sims[n * B + b0 + b];
        const float a = fabsf(s) + 1e-7f;
        s_er[n * 17 + b]  = expf(s);       // P(right) = exp(log-prob)
        s_elp[n * 17 + b] = -expm1f(-a);   // P(left)  = 1 - exp(-(|s|+eps))
    }
    __syncthreads();

    // ---- Phase B: per-leaf path products -> EW[leaf][b] ----
    {
        const int leaf = threadIdx.x;   // 256 threads == 256 leaves
        for (int b = 0; b < BT; b++) {
            float w = 1.0f;
            int node = 0;
#pragma unroll
            for (int lvl = 0; lvl < DEPTH; lvl++) {
                const int bit = (leaf >> (7 - lvl)) & 1;
                const float f = bit ? s_er[node * 17 + b] : s_elp[node * 17 + b];
                w *= f;
                node = 2 * node + 1 + bit;
            }
            s_ew[leaf * 20 + b] = w;
        }
    }
    __syncthreads();

    // ---- Phase C: out[b,c] = log( sum_k EW[b,k] * EL[k,c] ) ----
    const int t  = threadIdx.x;
    const int cg = t % 50;       // 50 class-quads  -> c0 = 4*cg
    const int bg = t / 50;       // 4 batch-quads   -> b  = 4*bg + i
    const bool active = (t < 200);

    unsigned long long acc[4][2];
#pragma unroll
    for (int i = 0; i < 4; i++) { acc[i][0] = 0ull; acc[i][1] = 0ull; }

    const float4* ew4 = (const float4*)s_ew;     // stride 5 float4 per leaf

    for (int k0 = 0; k0 < NL; k0 += 64) {
        __syncthreads();
        // stage EL chunk [k0 .. k0+63] into smem (coalesced float4 copy)
        const float4* src = (const float4*)(g_EL + k0 * NCLS);
        for (int i = threadIdx.x; i < 64 * 50; i += 256) {
            const int r = i / 50, q = i % 50;
            ((float4*)(s_els + r * 204))[q] = src[r * 50 + q];
        }
        __syncthreads();

        if (active) {
            const float4* el4 = (const float4*)s_els;  // stride 51 float4 per k
#pragma unroll 4
            for (int kk = 0; kk < 64; kk++) {
                const float4 w4 = ew4[(k0 + kk) * 5 + bg];
                const float4 e4 = el4[kk * 51 + cg];
                const unsigned long long e01 = pk2(e4.x, e4.y);
                const unsigned long long e23 = pk2(e4.z, e4.w);
                unsigned long long wd;
                wd = pk2(w4.x, w4.x);
                acc[0][0] = fma2(wd, e01, acc[0][0]);
                acc[0][1] = fma2(wd, e23, acc[0][1]);
                wd = pk2(w4.y, w4.y);
                acc[1][0] = fma2(wd, e01, acc[1][0]);
                acc[1][1] = fma2(wd, e23, acc[1][1]);
                wd = pk2(w4.z, w4.z);
                acc[2][0] = fma2(wd, e01, acc[2][0]);
                acc[2][1] = fma2(wd, e23, acc[2][1]);
                wd = pk2(w4.w, w4.w);
                acc[3][0] = fma2(wd, e01, acc[3][0]);
                acc[3][1] = fma2(wd, e23, acc[3][1]);
            }
        }
    }

    // ---- Epilogue: log + coalesced float4 store ----
    if (active) {
        const int c0 = cg * 4;
#pragma unroll
        for (int i = 0; i < 4; i++) {
            const int b = b0 + bg * 4 + i;
            if (b < B) {
                float x0, x1, x2, x3;
                upk2(acc[i][0], x0, x1);
                upk2(acc[i][1], x2, x3);
                float4 o;
                o.x = logf(x0); o.y = logf(x1); o.z = logf(x2); o.w = logf(x3);
                *((float4*)(out + (size_t)b * NCLS + c0)) = o;
            }
        }
    }
}

extern "C" void kernel_launch(void* const* d_in, const int* in_sizes, int n_in,
                              void* d_out, int out_size) {
    const float* sims   = (const float*)d_in[0];
    const float* logits = (const float*)d_in[1];
    int sims_sz = in_sizes[0];
    // defensive: identify inputs by size (sims = 255*B, logits = 256*200)
    if (n_in >= 2 && in_sizes[0] == NL * NCLS) {
        const float* tmp = sims; sims = logits; logits = tmp;
        sims_sz = in_sizes[1];
    }
    const int B = sims_sz / NN;   // 2048

    const int smem_bytes = SMEM_FLOATS * (int)sizeof(float);
    cudaFuncSetAttribute(tree_gemm_kernel,
                         cudaFuncAttributeMaxDynamicSharedMemorySize, smem_bytes);

    leaf_softmax_kernel<<<NL / 8, 256>>>(logits);
    tree_gemm_kernel<<<(B + BT - 1) / BT, 256, smem_bytes>>>(sims, (float*)d_out, B);
}

// round 6
// speedup vs baseline: 1.3536x; 1.3536x over previous
#include <cuda_runtime.h>
#include <math.h>
#include <stdint.h>

// Problem constants (fixed shapes per reference)
#define DEPTH    8
#define NN       255      // internal nodes
#define NL       256      // leaves (K dim)
#define NCLS     200      // classes
#define BT       16       // batch tile per block
#define KS       4        // k-split factor
#define KCH      (NL / KS) // 64 k per split

// ---- smem layout (floats) ----
// s_ew : [256 leaves][stride 20]  = 5120 floats (20,480 B)
// s_el : [256 k][stride 200]     = 51200 floats (204,800 B)
// er/elp overlay lives inside s_el before EL is staged.
// partials for the k-split combine reuse the FRONT of s_el after the mainloop.
#define EW_FLOATS   (NL * 20)                 // 5120
#define EL_FLOATS   (NL * NCLS)               // 51200
#define SMEM_FLOATS (EW_FLOATS + EL_FLOATS)   // 56320 floats = 225,280 B

__device__ __align__(16) float g_EL[NL * NCLS];

// ---------------- packed f32x2 helpers (Blackwell) ----------------
__device__ __forceinline__ unsigned long long pk2(float lo, float hi) {
    unsigned long long r;
    asm("mov.b64 %0, {%1, %2};" : "=l"(r) : "f"(lo), "f"(hi));
    return r;
}
__device__ __forceinline__ unsigned long long fma2(unsigned long long a,
                                                   unsigned long long b,
                                                   unsigned long long c) {
    unsigned long long d;
    asm("fma.rn.f32x2 %0, %1, %2, %3;" : "=l"(d) : "l"(a), "l"(b), "l"(c));
    return d;
}
__device__ __forceinline__ void upk2(unsigned long long v, float& lo, float& hi) {
    asm("mov.b64 {%0, %1}, %2;" : "=f"(lo), "=f"(hi) : "l"(v));
}

// ---------------- kernel 1: row softmax of leaf_logits ----------------
__global__ void leaf_softmax_kernel(const float* __restrict__ logits) {
    const int wid  = threadIdx.x >> 5;
    const int lane = threadIdx.x & 31;
    const int leaf = blockIdx.x * 8 + wid;
    const float* row = logits + leaf * NCLS;

    float v[7];
    float m = -INFINITY;
#pragma unroll
    for (int i = 0; i < 7; i++) {
        int c = lane + 32 * i;
        v[i] = (c < NCLS) ? row[c] : -INFINITY;
        m = fmaxf(m, v[i]);
    }
#pragma unroll
    for (int o = 16; o; o >>= 1) m = fmaxf(m, __shfl_xor_sync(0xffffffffu, m, o));

    float s = 0.f;
#pragma unroll
    for (int i = 0; i < 7; i++) {
        v[i] = expf(v[i] - m);
        s += v[i];
    }
#pragma unroll
    for (int o = 16; o; o >>= 1) s += __shfl_xor_sync(0xffffffffu, s, o);

    const float r = 1.0f / s;
#pragma unroll
    for (int i = 0; i < 7; i++) {
        int c = lane + 32 * i;
        if (c < NCLS) g_EL[leaf * NCLS + c] = v[i] * r;
    }
}

// ---------------- kernel 2: fused tree-walk + GEMM + log ----------------
// grid = 128 blocks (B/16), 1024 threads (32 warps). K split 4-ways.
__global__ __launch_bounds__(1024, 1)
void tree_gemm_kernel(const float* __restrict__ sims, float* __restrict__ out,
                      const int B) {
    extern __shared__ float sm[];
    float* s_ew = sm;                 // [leaf][b], stride 20 floats
    float* s_el = sm + EW_FLOATS;     // [k][c],   stride 200 floats
    float* s_er  = s_el;              // [node][b], stride 20 (overlay)
    float* s_elp = s_el + 5120;       // [node][b], stride 20 (overlay)

    const int tid = threadIdx.x;
    const int b0  = blockIdx.x * BT;

    // ---- Phase A: sims tile -> routing probabilities ----
    for (int i = tid; i < NN * BT; i += 1024) {
        const int n = i >> 4;
        const int b = i & 15;
        float s = 0.0f;
        if (b0 + b < B) s = sims[n * B + b0 + b];
        const float a = fabsf(s) + 1e-7f;
        s_er[n * 20 + b]  = expf(s);       // P(right)
        s_elp[n * 20 + b] = -expm1f(-a);   // P(left)
    }
    __syncthreads();

    // ---- Phase B: per-leaf path products -> EW[leaf][b] ----
    {
        const int leaf = tid & 255;
        const int bq   = tid >> 8;          // 0..3 -> batches bq*4..bq*4+3
        float4 w = make_float4(1.f, 1.f, 1.f, 1.f);
        int node = 0;
#pragma unroll
        for (int lvl = 0; lvl < DEPTH; lvl++) {
            const int bit = (leaf >> (7 - lvl)) & 1;
            const float* base = bit ? s_er : s_elp;
            const float4 f = *(const float4*)(base + node * 20 + bq * 4);
            w.x *= f.x; w.y *= f.y; w.z *= f.z; w.w *= f.w;
            node = 2 * node + 1 + bit;
        }
        *(float4*)(s_ew + leaf * 20 + bq * 4) = w;
    }
    __syncthreads();

    // ---- stage ALL of EL into smem (overwrites er/elp) ----
    {
        const float4* src = (const float4*)g_EL;
        float4*       dst = (float4*)s_el;
#pragma unroll
        for (int i = 0; i < 12; i++)
            dst[tid + i * 1024] = src[tid + i * 1024];
        const int tail = tid + 12 * 1024;
        if (tail < EL_FLOATS / 4) dst[tail] = src[tail];
    }
    __syncthreads();

    // ---- Phase C: k-split GEMM, no barriers inside ----
    // bg = tid&3 (batch quad), cg = (tid>>2)&63 (class quad, active<50),
    // ks = tid>>8. Warp = 8 consecutive cg x 4 bg -> EL read ~one 128B window
    // (broadcast), EW read one 64B window.
    const int bg = tid & 3;
    const int cg = (tid >> 2) & 63;
    const int ks = tid >> 8;
    const bool active = (cg < 50);

    unsigned long long acc[4][2];
#pragma unroll
    for (int i = 0; i < 4; i++) { acc[i][0] = 0ull; acc[i][1] = 0ull; }

    if (active) {
        const float4* ew4 = (const float4*)s_ew;   // + k*5 + bg
        const float4* el4 = (const float4*)s_el;   // + k*50 + cg
        const int kbase = ks * KCH;
#pragma unroll 8
        for (int kk = 0; kk < KCH; kk++) {
            const int k = kbase + kk;
            const float4 w4 = ew4[k * 5 + bg];
            const float4 e4 = el4[k * 50 + cg];
            const unsigned long long e01 = pk2(e4.x, e4.y);
            const unsigned long long e23 = pk2(e4.z, e4.w);
            unsigned long long wd;
            wd = pk2(w4.x, w4.x);
            acc[0][0] = fma2(wd, e01, acc[0][0]);
            acc[0][1] = fma2(wd, e23, acc[0][1]);
            wd = pk2(w4.y, w4.y);
            acc[1][0] = fma2(wd, e01, acc[1][0]);
            acc[1][1] = fma2(wd, e23, acc[1][1]);
            wd = pk2(w4.z, w4.z);
            acc[2][0] = fma2(wd, e01, acc[2][0]);
            acc[2][1] = fma2(wd, e23, acc[2][1]);
            wd = pk2(w4.w, w4.w);
            acc[3][0] = fma2(wd, e01, acc[3][0]);
            acc[3][1] = fma2(wd, e23, acc[3][1]);
        }
    }

    // ---- combine k-split partials through smem (reuse s_el front) ----
    __syncthreads();   // all reads of s_ew/s_el done
    float* part = s_el;   // 600 threads * 16 floats = 9600 floats << 51200
    if (active && ks > 0) {
        float* p = part + (((ks - 1) * 200) + (cg * 4 + bg)) * 16;
        float x[16];
        upk2(acc[0][0], x[0],  x[1]);  upk2(acc[0][1], x[2],  x[3]);
        upk2(acc[1][0], x[4],  x[5]);  upk2(acc[1][1], x[6],  x[7]);
        upk2(acc[2][0], x[8],  x[9]);  upk2(acc[2][1], x[10], x[11]);
        upk2(acc[3][0], x[12], x[13]); upk2(acc[3][1], x[14], x[15]);
        ((float4*)p)[0] = make_float4(x[0],  x[1],  x[2],  x[3]);
        ((float4*)p)[1] = make_float4(x[4],  x[5],  x[6],  x[7]);
        ((float4*)p)[2] = make_float4(x[8],  x[9],  x[10], x[11]);
        ((float4*)p)[3] = make_float4(x[12], x[13], x[14], x[15]);
    }
    __syncthreads();

    // ---- Epilogue: ks==0 threads reduce + log + coalesced float4 store ----
    if (active && ks == 0) {
        float x[16];
        upk2(acc[0][0], x[0],  x[1]);  upk2(acc[0][1], x[2],  x[3]);
        upk2(acc[1][0], x[4],  x[5]);  upk2(acc[1][1], x[6],  x[7]);
        upk2(acc[2][0], x[8],  x[9]);  upk2(acc[2][1], x[10], x[11]);
        upk2(acc[3][0], x[12], x[13]); upk2(acc[3][1], x[14], x[15]);
#pragma unroll
        for (int s = 1; s < KS; s++) {
            const float4* p = (const float4*)(part + (((s - 1) * 200) + (cg * 4 + bg)) * 16);
            const float4 a0 = p[0], a1 = p[1], a2 = p[2], a3 = p[3];
            x[0]  += a0.x; x[1]  += a0.y; x[2]  += a0.z; x[3]  += a0.w;
            x[4]  += a1.x; x[5]  += a1.y; x[6]  += a1.z; x[7]  += a1.w;
            x[8]  += a2.x; x[9]  += a2.y; x[10] += a2.z; x[11] += a2.w;
            x[12] += a3.x; x[13] += a3.y; x[14] += a3.z; x[15] += a3.w;
        }
        const int c0 = cg * 4;
#pragma unroll
        for (int i = 0; i < 4; i++) {
            const int b = b0 + bg * 4 + i;
            if (b < B) {
                float4 o;
                o.x = logf(x[i * 4 + 0]);
                o.y = logf(x[i * 4 + 1]);
                o.z = logf(x[i * 4 + 2]);
                o.w = logf(x[i * 4 + 3]);
                *((float4*)(out + (size_t)b * NCLS + c0)) = o;
            }
        }
    }
}

extern "C" void kernel_launch(void* const* d_in, const int* in_sizes, int n_in,
                              void* d_out, int out_size) {
    const float* sims   = (const float*)d_in[0];
    const float* logits = (const float*)d_in[1];
    int sims_sz = in_sizes[0];
    if (n_in >= 2 && in_sizes[0] == NL * NCLS) {   // defensive input-order check
        const float* tmp = sims; sims = logits; logits = tmp;
        sims_sz = in_sizes[1];
    }
    const int B = sims_sz / NN;   // 2048

    const int smem_bytes = SMEM_FLOATS * (int)sizeof(float);   // 225,280 B
    cudaFuncSetAttribute(tree_gemm_kernel,
                         cudaFuncAttributeMaxDynamicSharedMemorySize, smem_bytes);

    leaf_softmax_kernel<<<NL / 8, 256>>>(logits);
    tree_gemm_kernel<<<(B + BT - 1) / BT, 1024, smem_bytes>>>(sims, (float*)d_out, B);
}